// round 15
// baseline (speedup 1.0000x reference)
#include <cuda_runtime.h>
#include <cuda_bf16.h>
#include <cuda_fp16.h>
#include <cstdint>
#include <cstddef>

namespace cfg {
constexpr int B = 4;
constexpr int T = 512;
constexpr int H = 768;
constexpr int N = 256;
constexpr int S = 16;
constexpr int NERD = 32;
constexpr int D = 800;          // H + NERD
constexpr int R = 15;
constexpr int NE = 64;
constexpr int MM = 8;
constexpr int P = 1024;
constexpr int E = 4096;
constexpr int OUT = 97;
constexpr int EE = 1600;        // 2*D
constexpr int HID = 3200;       // 2*EE
constexpr int KG = 12800;       // 16*D  ([S_0..S_14 | h])
constexpr int KSPLIT = 12000;   // R*D
constexpr int NPG = 896;        // GNN N padded to 7*128
}

// ---------------- scratch (device globals; no runtime allocation) ----------------
__device__ float g_docproj[cfg::B * cfg::D];
__device__ float g_h0[cfg::B * cfg::N * cfg::D];
__device__ float g_h1[cfg::B * cfg::N * cfg::D];
__device__ float g_h2[cfg::B * cfg::N * cfg::D];
__device__ __half g_A16[(size_t)cfg::B * cfg::N * 16 * cfg::D];          // fp16 agg buffer
__device__ __half g_Wg16_hi[2][(size_t)cfg::NPG * cfg::KG];              // GNN W^T fp16
__device__ __half g_ent16_hi[cfg::B * cfg::NE * cfg::EE];
__device__ __half g_ent16_lo[cfg::B * cfg::NE * cfg::EE];
__device__ __half g_W1linT16_hi[(size_t)2 * cfg::HID * cfg::EE];         // [6400][1600]
__device__ __half g_W1nlT16_hi[(size_t)cfg::HID * cfg::HID];             // [3200][3200]
__device__ __half g_W2T16_hi[128 * cfg::HID];
__device__ float g_entAB[(size_t)cfg::B * cfg::NE * 2 * cfg::HID];       // [256][6400]
__device__ __half g_nlh[(size_t)cfg::B * cfg::P * cfg::HID];             // fp16 single
__device__ __half g_hid16[(size_t)cfg::B * cfg::P * cfg::HID];           // fp16 single
__device__ float g_gnnacc[(size_t)cfg::B * cfg::N * cfg::NPG];           // split-K accum
__device__ float g_outacc[(size_t)cfg::B * cfg::P * cfg::OUT];

// ================= helpers =================
__device__ __forceinline__ uint32_t smem_u32(const void* p) {
    uint32_t a;
    asm("{ .reg .u64 t; cvta.to.shared.u64 t, %1; cvt.u32.u64 %0, t; }"
        : "=r"(a) : "l"(p));
    return a;
}
__device__ __forceinline__ void ldsm4(uint32_t* r, uint32_t addr) {
    asm volatile("ldmatrix.sync.aligned.m8n8.x4.shared.b16 {%0,%1,%2,%3}, [%4];"
                 : "=r"(r[0]), "=r"(r[1]), "=r"(r[2]), "=r"(r[3]) : "r"(addr));
}
__device__ __forceinline__ void mma_f16(float* c, const uint32_t* a,
                                        uint32_t b0, uint32_t b1) {
    asm volatile(
        "mma.sync.aligned.m16n8k16.row.col.f32.f16.f16.f32 "
        "{%0,%1,%2,%3}, {%4,%5,%6,%7}, {%8,%9}, {%0,%1,%2,%3};"
        : "+f"(c[0]), "+f"(c[1]), "+f"(c[2]), "+f"(c[3])
        : "r"(a[0]), "r"(a[1]), "r"(a[2]), "r"(a[3]), "r"(b0), "r"(b1));
}
__device__ __forceinline__ void split_f16(float x, __half& h, __half& l) {
    h = __float2half_rn(x);
    l = __float2half_rn(x - __half2float(h));
}
__device__ __forceinline__ uint32_t pkhf(__half a, __half b) {
    __half2 t = __halves2half2(a, b);
    return *reinterpret_cast<uint32_t*>(&t);
}
__device__ __forceinline__ void cpa16(uint32_t dst, const void* src) {
    asm volatile("cp.async.cg.shared.global [%0], [%1], 16;" :: "r"(dst), "l"(src));
}
__device__ __forceinline__ void cpa_commit() {
    asm volatile("cp.async.commit_group;" ::: "memory");
}
template <int NN>
__device__ __forceinline__ void cpa_wait() {
    asm volatile("cp.async.wait_group %0;" :: "n"(NN) : "memory");
}

// =====================================================================
// fp16 GEMM: A single fp16 [M][Kstride], B fp16 [N][Kstride] (W^T),
// B with BTERMS in {1, 2}. BK=64, 2-stage. BM in {128, 256}.
// MODE 4: atomicAdd(Cf, acc)    (split-K over blockIdx.z)
// MODE 2: pair epilogue -> single fp16 C16   (z = 1)
// =====================================================================
template <int BM, int BN, int MODE, int BTERMS>
__global__ void __launch_bounds__(256)
k_mm2(const __half* __restrict__ A16,
      const __half* __restrict__ Bhi, const __half* __restrict__ Blo,
      int Kstride, int Klen, int Ncol,
      const float* __restrict__ bias, float* __restrict__ Cf,
      __half* __restrict__ C16,
      const float* __restrict__ gAB, const int* __restrict__ pairs) {
    using namespace cfg;
    constexpr int BK = 64;
    constexpr int WNG = (BN == 128) ? 4 : 2;
    constexpr int WMG = 8 / WNG;
    constexpr int WTM = BM / WMG;
    constexpr int WTN = BN / WNG;        // 32
    constexpr int MATOMS = WTM / 16;
    constexpr int NAT16 = WTN / 16;      // 2
    constexpr int NATOMS = WTN / 8;      // 4
    constexpr int RB = BM * 128;         // A region per stage
    constexpr int RBB = BN * 128;        // B half region per stage
    constexpr int SB = RB + BTERMS * RBB;

    extern __shared__ char smem[];
    const uint32_t sbase = smem_u32(smem);
    const int tid = threadIdx.x;
    const int wid = tid >> 5, lane = tid & 31;
    const int wn = wid % WNG, wm = wid / WNG;
    const int bm0 = blockIdx.y * BM, bn0 = blockIdx.x * BN;
    const int lrow = lane & 15, lhalf = lane >> 4;
    const int kofs = blockIdx.z * Klen;

    float acc[MATOMS][NATOMS][4];
#pragma unroll
    for (int i = 0; i < MATOMS; i++)
#pragma unroll
        for (int j = 0; j < NATOMS; j++)
#pragma unroll
            for (int q = 0; q < 4; q++) acc[i][j][q] = 0.f;

    const __half* Ap = A16 + (size_t)bm0 * Kstride + kofs;
    const __half* Bh = Bhi + (size_t)bn0 * Kstride + kofs;
    const __half* Bl = (BTERMS == 2) ? Blo + (size_t)bn0 * Kstride + kofs : nullptr;

    auto load_stage = [&](int s, int k0) {
        uint32_t base = sbase + s * SB;
#pragma unroll
        for (int i = 0; i < BM * 8 / 256; i++) {
            int f = tid + i * 256;
            int row = f >> 3, g = f & 7;
            uint32_t d = base + row * 128 + ((g ^ (row & 7)) << 4);
            cpa16(d, Ap + (size_t)row * Kstride + k0 + g * 8);
        }
#pragma unroll
        for (int i = 0; i < BN * 8 / 256; i++) {
            int f = tid + i * 256;
            int row = f >> 3, g = f & 7;
            uint32_t d = base + RB + row * 128 + ((g ^ (row & 7)) << 4);
            size_t so = (size_t)row * Kstride + k0 + g * 8;
            cpa16(d, Bh + so);
            if (BTERMS == 2) cpa16(d + RBB, Bl + so);
        }
    };

    const int nch = Klen / BK;
    load_stage(0, 0);
    cpa_commit();

    for (int ch = 0; ch < nch; ch++) {
        if (ch + 1 < nch) {
            load_stage((ch + 1) & 1, (ch + 1) * BK);
            cpa_commit();
            cpa_wait<1>();
        } else {
            cpa_wait<0>();
        }
        __syncthreads();

        uint32_t sA = sbase + (ch & 1) * SB;
        uint32_t sB = sA + RB;
#pragma unroll
        for (int s = 0; s < 4; s++) {
            uint32_t af[MATOMS][4];
#pragma unroll
            for (int ma = 0; ma < MATOMS; ma++) {
                int row = wm * WTM + ma * 16 + lrow;
                uint32_t off = sA + row * 128 + (((s * 2 + lhalf) ^ (row & 7)) << 4);
                ldsm4(af[ma], off);
            }
            uint32_t bh[NAT16][4], bl[NAT16][4];
#pragma unroll
            for (int ng = 0; ng < NAT16; ng++) {
                int rb = wn * WTN + ng * 16 + lrow;
                uint32_t off = sB + rb * 128 + (((s * 2 + lhalf) ^ (rb & 7)) << 4);
                ldsm4(bh[ng], off);
                if (BTERMS == 2) ldsm4(bl[ng], off + RBB);
            }
#pragma unroll
            for (int ma = 0; ma < MATOMS; ma++)
#pragma unroll
                for (int na = 0; na < NATOMS; na++)
                    mma_f16(acc[ma][na], af[ma], bh[na >> 1][na & 1],
                            bh[na >> 1][2 + (na & 1)]);
            if (BTERMS == 2) {
#pragma unroll
                for (int ma = 0; ma < MATOMS; ma++)
#pragma unroll
                    for (int na = 0; na < NATOMS; na++)
                        mma_f16(acc[ma][na], af[ma], bl[na >> 1][na & 1],
                                bl[na >> 1][2 + (na & 1)]);
            }
        }
        __syncthreads();
    }

    const int gid = lane >> 2, tig = lane & 3;
#pragma unroll
    for (int ma = 0; ma < MATOMS; ma++) {
        int rowbase = bm0 + wm * WTM + ma * 16;
#pragma unroll
        for (int na = 0; na < NATOMS; na++) {
            int col0 = bn0 + wn * WTN + na * 8 + 2 * tig;
#pragma unroll
            for (int half = 0; half < 2; half++) {
                int row = rowbase + gid + half * 8;
                float v0 = acc[ma][na][half * 2 + 0];
                float v1 = acc[ma][na][half * 2 + 1];
                if (MODE == 2) {
                    int b = row >> 10;          // row = b*P + p, P = 1024
                    int pp = row & 1023;
                    int p0 = pairs[(b * P + pp) * 2 + 0];
                    int p1 = pairs[(b * P + pp) * 2 + 1];
                    const float* ga = gAB + (size_t)(b * NE + p0) * (2 * HID);
                    const float* gb = gAB + (size_t)(b * NE + p1) * (2 * HID) + HID;
                    float r0 = fmaxf(v0 + ga[col0] + gb[col0] + bias[col0], 0.f);
                    float r1 = fmaxf(v1 + ga[col0 + 1] + gb[col0 + 1] + bias[col0 + 1], 0.f);
                    size_t o = (size_t)row * HID + col0;
                    *reinterpret_cast<uint32_t*>(C16 + o) =
                        pkhf(__float2half_rn(r0), __float2half_rn(r1));
                } else {  // MODE 4
                    if (col0 < Ncol)
                        atomicAdd(&Cf[(size_t)row * Ncol + col0], v0);
                    if (col0 + 1 < Ncol)
                        atomicAdd(&Cf[(size_t)row * Ncol + col0 + 1], v1);
                }
            }
        }
    }
}

// ---------------- zero f32 buffer (len % 4 == 0) ----------------
__global__ void k_zero(float* __restrict__ p, int n4) {
    int i = blockIdx.x * blockDim.x + threadIdx.x;
    if (i < n4) reinterpret_cast<float4*>(p)[i] = make_float4(0.f, 0.f, 0.f, 0.f);
}

// ---------------- GNN epilogue: h = relu(acc + bias) ----------------
__global__ void k_epignn(const float* __restrict__ acc, const float* __restrict__ bias,
                         float* __restrict__ h) {
    using namespace cfg;
    int i = blockIdx.x * blockDim.x + threadIdx.x;   // over B*N*D
    int row = i / D, col = i - row * D;
    h[i] = fmaxf(acc[(size_t)row * NPG + col] + bias[col], 0.f);
}

// ---------------- out epilogue: out = acc + b2 ----------------
__global__ void k_epiout(const float* __restrict__ acc, const float* __restrict__ b2,
                         float* __restrict__ out, int total) {
    using namespace cfg;
    int i = blockIdx.x * blockDim.x + threadIdx.x;
    if (i < total) out[i] = acc[i] + b2[i % OUT];
}

// ---------------- weight transpose + split (fp16, with Ksplit) ----------------
__global__ void k_transW16(const float* __restrict__ W0, const float* __restrict__ Wsf,
                           int Ksplit, int K, int Nsrc,
                           __half* __restrict__ Thi, __half* __restrict__ Tlo) {
    __shared__ float t[32][33];
    int k0 = blockIdx.x * 32, n0 = blockIdx.y * 32;
    int tx = threadIdx.x, ty = threadIdx.y;
#pragma unroll
    for (int i = 0; i < 4; i++) {
        int k = k0 + ty + i * 8;
        int n = n0 + tx;
        const float* row = (k < Ksplit) ? W0 + (size_t)k * Nsrc
                                        : Wsf + (size_t)(k - Ksplit) * Nsrc;
        t[ty + i * 8][tx] = (n < Nsrc) ? row[n] : 0.f;
    }
    __syncthreads();
#pragma unroll
    for (int i = 0; i < 4; i++) {
        int n = n0 + ty + i * 8;
        int k = k0 + tx;
        float v = t[tx][ty + i * 8];
        __half h, l;
        split_f16(v, h, l);
        Thi[(size_t)n * K + k] = h;
        if (Tlo) Tlo[(size_t)n * K + k] = l;
    }
}

// ---------------- doc projection ----------------
__global__ void k_docproj(const float* __restrict__ cls, const float* __restrict__ W,
                          const float* __restrict__ bvec, float* __restrict__ out) {
    using namespace cfg;
    int b = blockIdx.y;
    int d = blockIdx.x * blockDim.x + threadIdx.x;
    if (d >= D) return;
    float acc = bvec[d];
    const float* c = cls + b * H;
    for (int h = 0; h < H; h++) acc = fmaf(c[h], W[(size_t)h * D + d], acc);
    out[b * D + d] = fmaxf(acc, 0.f);
}

// ---------------- node features h0 ----------------
__global__ void k_node(const float* __restrict__ token, const float* __restrict__ cls,
                       const int* __restrict__ pos, const float* __restrict__ smask,
                       const int* __restrict__ ner, const float* __restrict__ nmask,
                       const int* __restrict__ ment, const float* __restrict__ nerEmb,
                       const float* __restrict__ docproj, float* __restrict__ h0) {
    using namespace cfg;
    const int n = blockIdx.x, b = blockIdx.y;
    __shared__ int sp[S];
    __shared__ float sm[S];
    int tid = threadIdx.x;
    if (tid < S) {
        sp[tid] = pos[(b * N + n) * S + tid];
        sm[tid] = smask[(b * N + n) * S + tid];
    }
    __syncthreads();
    float* dst = h0 + (size_t)(b * N + n) * D;
    if (n == ment[b]) {
        for (int d = tid; d < D; d += blockDim.x) dst[d] = docproj[b * D + d];
        return;
    }
    float den = 0.1f;
#pragma unroll
    for (int s = 0; s < S; s++) den += sm[s];
    float nm = nmask[b * N + n];
    int nerIdx = ner[b * N + n];
    for (int d = tid; d < D; d += blockDim.x) {
        float v;
        if (d < H) {
            float acc = 0.f;
#pragma unroll
            for (int s = 0; s < S; s++)
                acc = fmaf(token[((size_t)b * T + sp[s]) * H + d], sm[s], acc);
            v = acc / den + cls[b * H + d];
        } else {
            v = nerEmb[nerIdx * NERD + (d - H)];
        }
        dst[d] = v * nm;
    }
}

// ---------------- init A16: slots 0..14 = 0, slot 15 = fp16(h); 2 elems/thread ----------------
__global__ void k_initA16(const float* __restrict__ hin, __half* __restrict__ A) {
    using namespace cfg;
    size_t i2 = (size_t)blockIdx.x * blockDim.x + threadIdx.x;   // half2 index
    size_t idx = i2 * 2;
    int d = (int)(idx % D);
    size_t rest = idx / D;
    int r = (int)(rest & 15);
    size_t bn = rest >> 4;
    __half2 v = __halves2half2(__float2half_rn(0.f), __float2half_rn(0.f));
    if (r == 15) {
        const float* h = hin + bn * D + d;
        v = __halves2half2(__float2half_rn(h[0]), __float2half_rn(h[1]));
    }
    reinterpret_cast<__half2*>(A)[i2] = v;
}

// ---------------- edge scatter (fp16): A[b,dst,rel,:] += h[b,src,:] ----------------
__global__ void k_scatter16(const float* __restrict__ hin, const int* __restrict__ src,
                            const int* __restrict__ dst, const int* __restrict__ rel,
                            __half* __restrict__ A) {
    using namespace cfg;
    int e = blockIdx.x, b = blockIdx.y;
    int sIdx = src[b * E + e];
    int dIdx = dst[b * E + e];
    int r = rel[b * E + e];
    const float* hrow = hin + (size_t)(b * N + sIdx) * D;
    __half2* arow = reinterpret_cast<__half2*>(
        A + ((size_t)(b * N + dIdx) * 16 + r) * D);
    for (int d2 = threadIdx.x; d2 < D / 2; d2 += blockDim.x) {
        float2 v = *reinterpret_cast<const float2*>(hrow + d2 * 2);
        atomicAdd(&arow[d2],
                  __halves2half2(__float2half_rn(v.x), __float2half_rn(v.y)));
    }
}

// ---------------- entity pooling -> hi/lo fp16 ----------------
__global__ void k_ent(const float* __restrict__ h1, const float* __restrict__ h2,
                      const int* __restrict__ e2m, const float* __restrict__ e2mask,
                      __half* __restrict__ enthi, __half* __restrict__ entlo) {
    using namespace cfg;
    int i = blockIdx.x, b = blockIdx.y;
    __shared__ int idxs[MM];
    __shared__ float mk[MM];
    int tid = threadIdx.x;
    if (tid < MM) {
        idxs[tid] = e2m[(b * NE + i) * MM + tid];
        mk[tid] = e2mask[(b * NE + i) * MM + tid];
    }
    __syncthreads();
    float den = 1e-7f;
#pragma unroll
    for (int j = 0; j < MM; j++) den += mk[j];
    for (int c = tid; c < EE; c += blockDim.x) {
        float acc = 0.f;
#pragma unroll
        for (int j = 0; j < MM; j++) {
            int id = idxs[j];
            if (id > 0) {
                float v = (c < D) ? h1[(size_t)(b * N + id - 1) * D + c]
                                  : h2[(size_t)(b * N + id - 1) * D + (c - D)];
                acc = fmaf(v, mk[j], acc);
            }
        }
        float r = acc / den;
        __half h, l;
        split_f16(r, h, l);
        enthi[(size_t)(b * NE + i) * EE + c] = h;
        entlo[(size_t)(b * NE + i) * EE + c] = l;
    }
}

// ---------------- per-pair nonlinear features -> single fp16 ----------------
__global__ void k_nl(const __half* __restrict__ enthi, const __half* __restrict__ entlo,
                     const int* __restrict__ pairs, __half* __restrict__ nlh) {
    using namespace cfg;
    int p = blockIdx.x, b = blockIdx.y;
    int p0 = pairs[(b * P + p) * 2 + 0];
    int p1 = pairs[(b * P + p) * 2 + 1];
    const __half* hfh = enthi + (size_t)(b * NE + p0) * EE;
    const __half* hfl = entlo + (size_t)(b * NE + p0) * EE;
    const __half* tfh = enthi + (size_t)(b * NE + p1) * EE;
    const __half* tfl = entlo + (size_t)(b * NE + p1) * EE;
    size_t base = ((size_t)b * P + p) * HID;
    for (int c = threadIdx.x; c < EE; c += blockDim.x) {
        float a = __half2float(hfh[c]) + __half2float(hfl[c]);
        float t = __half2float(tfh[c]) + __half2float(tfl[c]);
        nlh[base + c] = __float2half_rn(fabsf(a - t));
        nlh[base + EE + c] = __float2half_rn(a * t);
    }
}

// ---------------- launch ----------------
extern "C" void kernel_launch(void* const* d_in, const int* in_sizes, int n_in,
                              void* d_out, int out_size) {
    using namespace cfg;
    const float* token     = (const float*)d_in[0];
    const float* cls       = (const float*)d_in[1];
    const int*   span_pos  = (const int*)d_in[2];
    const float* span_mask = (const float*)d_in[3];
    const int*   node_ner  = (const int*)d_in[4];
    const float* node_mask = (const float*)d_in[5];
    const int*   e2m       = (const int*)d_in[6];
    const float* e2m_mask  = (const float*)d_in[7];
    const int*   ent_pair  = (const int*)d_in[8];
    const int*   edge_src  = (const int*)d_in[9];
    const int*   edge_dst  = (const int*)d_in[10];
    const int*   edge_rel  = (const int*)d_in[11];
    const int*   ment_num  = (const int*)d_in[12];
    const float* nerEmb    = (const float*)d_in[13];
    const float* doc_W     = (const float*)d_in[14];
    const float* doc_b     = (const float*)d_in[15];
    const float* W_rel     = (const float*)d_in[16];
    const float* W_self    = (const float*)d_in[17];
    const float* gnn_b     = (const float*)d_in[18];
    const float* W1        = (const float*)d_in[19];
    const float* b1        = (const float*)d_in[20];
    const float* W2        = (const float*)d_in[21];
    const float* b2        = (const float*)d_in[22];
    float* out = (float*)d_out;
    (void)in_sizes; (void)n_in; (void)out_size;

    float *pdoc, *ph0, *ph1, *ph2, *pentAB, *pgnnacc, *poutacc;
    __half *pA16, *pWg16_hi, *pent16_hi, *pent16_lo;
    __half *pW1linT16_hi, *pW1nlT16_hi;
    __half *pW2T16_hi, *pnlh, *phid16;
    cudaGetSymbolAddress((void**)&pdoc,  g_docproj);
    cudaGetSymbolAddress((void**)&ph0,   g_h0);
    cudaGetSymbolAddress((void**)&ph1,   g_h1);
    cudaGetSymbolAddress((void**)&ph2,   g_h2);
    cudaGetSymbolAddress((void**)&pA16,  g_A16);
    cudaGetSymbolAddress((void**)&pWg16_hi, g_Wg16_hi);
    cudaGetSymbolAddress((void**)&pent16_hi, g_ent16_hi);
    cudaGetSymbolAddress((void**)&pent16_lo, g_ent16_lo);
    cudaGetSymbolAddress((void**)&pW1linT16_hi, g_W1linT16_hi);
    cudaGetSymbolAddress((void**)&pW1nlT16_hi, g_W1nlT16_hi);
    cudaGetSymbolAddress((void**)&pW2T16_hi, g_W2T16_hi);
    cudaGetSymbolAddress((void**)&pentAB, g_entAB);
    cudaGetSymbolAddress((void**)&pnlh, g_nlh);
    cudaGetSymbolAddress((void**)&phid16, g_hid16);
    cudaGetSymbolAddress((void**)&pgnnacc, g_gnnacc);
    cudaGetSymbolAddress((void**)&poutacc, g_outacc);

    constexpr int SMEMPAIR = 2 * (256 * 128 + 1 * 128 * 128);  // 98304 (BM=256,BN=128)
    constexpr int SMEM128  = 2 * (128 * 128 + 1 * 128 * 128);  // 65536 (BM=128,BN=128)
    constexpr int SMEMOUT  = 2 * (128 * 128 + 1 * 64 * 128);   // 49152 (BM=128,BN=64)
    cudaFuncSetAttribute(k_mm2<256, 128, 2, 1>,
                         cudaFuncAttributeMaxDynamicSharedMemorySize, SMEMPAIR);
    cudaFuncSetAttribute(k_mm2<128, 128, 4, 1>,
                         cudaFuncAttributeMaxDynamicSharedMemorySize, SMEM128);
    cudaFuncSetAttribute(k_mm2<128, 64, 4, 1>,
                         cudaFuncAttributeMaxDynamicSharedMemorySize, SMEMOUT);

    const dim3 tb(32, 8);

    // 0) one-shot weight transpose + fp16 convert (per launch)
    k_transW16<<<dim3(KG / 32, NPG / 32), tb>>>(W_rel, W_self, KSPLIT, KG, D,
                                                pWg16_hi, nullptr);
    k_transW16<<<dim3(KG / 32, NPG / 32), tb>>>(W_rel + (size_t)R * D * D,
                                                W_self + (size_t)D * D, KSPLIT, KG, D,
                                                pWg16_hi + (size_t)NPG * KG, nullptr);
    k_transW16<<<dim3(EE / 32, HID / 32), tb>>>(W1, W1, EE, EE, HID,
                                                pW1linT16_hi, nullptr);
    k_transW16<<<dim3(EE / 32, HID / 32), tb>>>(W1 + (size_t)EE * HID, W1, EE, EE, HID,
                                                pW1linT16_hi + (size_t)HID * EE, nullptr);
    k_transW16<<<dim3(HID / 32, HID / 32), tb>>>(W1 + (size_t)2 * EE * HID, W1,
                                                 HID, HID, HID,
                                                 pW1nlT16_hi, nullptr);
    k_transW16<<<dim3(HID / 32, 4), tb>>>(W2, W2, HID, HID, OUT,
                                          pW2T16_hi, nullptr);

    // 1) doc projection + node features
    k_docproj<<<dim3((D + 255) / 256, B), 256>>>(cls, doc_W, doc_b, pdoc);
    k_node<<<dim3(N, B), 256>>>(token, cls, span_pos, span_mask, node_ner, node_mask,
                                ment_num, nerEmb, pdoc, ph0);

    const size_t Atotal = (size_t)B * N * 16 * D;   // 13,107,200
    const int initBlocks = (int)(Atotal / 2 / 256); // half2-vectorized
    const int gnnaccN4 = B * N * NPG / 4;           // 229376
    const int entabN4 = B * NE * 2 * HID / 4;       // 409600
    const int outaccTotal = B * P * OUT;            // 397312
    const int gnnEpiBlocks = (B * N * D) / 256;     // 3200

    // 2) GNN layer 0 (fp16 1-term GEMM, BN=128 tiles, split-K z=4)
    k_initA16<<<initBlocks, 256>>>(ph0, pA16);
    k_scatter16<<<dim3(E, B), 256>>>(ph0, edge_src, edge_dst, edge_rel, pA16);
    k_zero<<<(gnnaccN4 + 255) / 256, 256>>>(pgnnacc, gnnaccN4);
    k_mm2<128, 128, 4, 1><<<dim3(NPG / 128, (B * N) / 128, 4), 256, SMEM128>>>(
        pA16, pWg16_hi, nullptr, KG, KG / 4, NPG, nullptr, pgnnacc,
        nullptr, nullptr, nullptr);
    k_epignn<<<gnnEpiBlocks, 256>>>(pgnnacc, gnn_b, ph1);

    // 3) GNN layer 1
    k_initA16<<<initBlocks, 256>>>(ph1, pA16);
    k_scatter16<<<dim3(E, B), 256>>>(ph1, edge_src, edge_dst, edge_rel, pA16);
    k_zero<<<(gnnaccN4 + 255) / 256, 256>>>(pgnnacc, gnnaccN4);
    k_mm2<128, 128, 4, 1><<<dim3(NPG / 128, (B * N) / 128, 4), 256, SMEM128>>>(
        pA16, pWg16_hi + (size_t)NPG * KG, nullptr,
        KG, KG / 4, NPG, nullptr, pgnnacc, nullptr, nullptr, nullptr);
    k_epignn<<<gnnEpiBlocks, 256>>>(pgnnacc, gnn_b + D, ph2);

    // 4) entity pooling (-> fp16 hi/lo)
    k_ent<<<dim3(NE, B), 256>>>(ph1, ph2, e2m, e2m_mask, pent16_hi, pent16_lo);

    // 5) linear halves of pair MLP (fp16 1-term, split-K z=5, atomic into entAB)
    k_zero<<<(entabN4 + 255) / 256, 256>>>(pentAB, entabN4);
    k_mm2<128, 128, 4, 1><<<dim3((2 * HID) / 128, (B * NE) / 128, 5), 256, SMEM128>>>(
        pent16_hi, pW1linT16_hi, nullptr, EE, EE / 5, 2 * HID,
        nullptr, pentAB, nullptr, nullptr, nullptr);

    // 6) nonlinear pair features + fp16 pair GEMM (BM=256) -> hid16
    k_nl<<<dim3(P, B), 256>>>(pent16_hi, pent16_lo, ent_pair, pnlh);
    k_mm2<256, 128, 2, 1><<<dim3(HID / 128, (B * P) / 256, 1), 256, SMEMPAIR>>>(
        pnlh, pW1nlT16_hi, nullptr, HID, HID, HID, b1, nullptr,
        phid16, pentAB, ent_pair);

    // 7) output layer: hid16 @ W2 (fp16 1-term, split-K z=5), then +b2 epilogue
    k_zero<<<(outaccTotal / 4 + 255) / 256, 256>>>(poutacc, outaccTotal / 4);
    k_mm2<128, 64, 4, 1><<<dim3(2, (B * P) / 128, 5), 256, SMEMOUT>>>(
        phid16, pW2T16_hi, nullptr, HID, HID / 5, OUT, nullptr, poutacc,
        nullptr, nullptr, nullptr);
    k_epiout<<<(outaccTotal + 255) / 256, 256>>>(poutacc, b2, out, outaccTotal);
}

// round 16
// speedup vs baseline: 1.0916x; 1.0916x over previous
#include <cuda_runtime.h>
#include <cuda_bf16.h>
#include <cuda_fp16.h>
#include <cstdint>
#include <cstddef>

namespace cfg {
constexpr int B = 4;
constexpr int T = 512;
constexpr int H = 768;
constexpr int N = 256;
constexpr int S = 16;
constexpr int NERD = 32;
constexpr int D = 800;          // H + NERD
constexpr int R = 15;
constexpr int NE = 64;
constexpr int MM = 8;
constexpr int P = 1024;
constexpr int E = 4096;
constexpr int OUT = 97;
constexpr int EE = 1600;        // 2*D
constexpr int HID = 3200;       // 2*EE
constexpr int KG = 12800;       // 16*D  ([S_0..S_14 | h])
constexpr int KSPLIT = 12000;   // R*D
constexpr int NPG = 832;        // GNN N padded to 13*64
}

// ---------------- scratch (device globals; no runtime allocation) ----------------
__device__ float g_docproj[cfg::B * cfg::D];
__device__ float g_h0[cfg::B * cfg::N * cfg::D];
__device__ float g_h1[cfg::B * cfg::N * cfg::D];
__device__ float g_h2[cfg::B * cfg::N * cfg::D];
__device__ __half g_A16[(size_t)cfg::B * cfg::N * 16 * cfg::D];          // fp16 agg buffer
__device__ __half g_Wg16_hi[2][(size_t)cfg::NPG * cfg::KG];              // GNN W^T fp16
__device__ __half g_ent16_hi[cfg::B * cfg::NE * cfg::EE];
__device__ __half g_ent16_lo[cfg::B * cfg::NE * cfg::EE];
__device__ __half g_W1linT16_hi[(size_t)2 * cfg::HID * cfg::EE];         // [6400][1600]
__device__ __half g_W1nlT16_hi[(size_t)cfg::HID * cfg::HID];             // [3200][3200]
__device__ __half g_W2T16_hi[128 * cfg::HID];
__device__ float g_entAB[(size_t)cfg::B * cfg::NE * 2 * cfg::HID];       // [256][6400]
__device__ __half g_nlh[(size_t)cfg::B * cfg::P * cfg::HID];             // fp16 single
__device__ __half g_hid16[(size_t)cfg::B * cfg::P * cfg::HID];           // fp16 single
__device__ float g_gnnacc[(size_t)cfg::B * cfg::N * cfg::NPG];           // split-K accum

// ================= helpers =================
__device__ __forceinline__ uint32_t smem_u32(const void* p) {
    uint32_t a;
    asm("{ .reg .u64 t; cvta.to.shared.u64 t, %1; cvt.u32.u64 %0, t; }"
        : "=r"(a) : "l"(p));
    return a;
}
__device__ __forceinline__ void ldsm4(uint32_t* r, uint32_t addr) {
    asm volatile("ldmatrix.sync.aligned.m8n8.x4.shared.b16 {%0,%1,%2,%3}, [%4];"
                 : "=r"(r[0]), "=r"(r[1]), "=r"(r[2]), "=r"(r[3]) : "r"(addr));
}
__device__ __forceinline__ void mma_f16(float* c, const uint32_t* a,
                                        uint32_t b0, uint32_t b1) {
    asm volatile(
        "mma.sync.aligned.m16n8k16.row.col.f32.f16.f16.f32 "
        "{%0,%1,%2,%3}, {%4,%5,%6,%7}, {%8,%9}, {%0,%1,%2,%3};"
        : "+f"(c[0]), "+f"(c[1]), "+f"(c[2]), "+f"(c[3])
        : "r"(a[0]), "r"(a[1]), "r"(a[2]), "r"(a[3]), "r"(b0), "r"(b1));
}
__device__ __forceinline__ void split_f16(float x, __half& h, __half& l) {
    h = __float2half_rn(x);
    l = __float2half_rn(x - __half2float(h));
}
__device__ __forceinline__ uint32_t pkhf(__half a, __half b) {
    __half2 t = __halves2half2(a, b);
    return *reinterpret_cast<uint32_t*>(&t);
}
__device__ __forceinline__ void cpa16(uint32_t dst, const void* src) {
    asm volatile("cp.async.cg.shared.global [%0], [%1], 16;" :: "r"(dst), "l"(src));
}
__device__ __forceinline__ void cpa_commit() {
    asm volatile("cp.async.commit_group;" ::: "memory");
}
template <int NN>
__device__ __forceinline__ void cpa_wait() {
    asm volatile("cp.async.wait_group %0;" :: "n"(NN) : "memory");
}

// =====================================================================
// fp16 GEMM (round-14 proven config): A single fp16 [M][Kstride],
// B fp16 [N][Kstride] (W^T). BM=128, BK=64, 2-stage, BTERMS=1.
// MODE 4: atomicAdd(Cf, acc)    (split-K over blockIdx.z)
// MODE 2: pair epilogue -> single fp16 C16   (z = 1)
// =====================================================================
template <int BN, int MODE>
__global__ void __launch_bounds__(256)
k_mm2(const __half* __restrict__ A16,
      const __half* __restrict__ Bhi,
      int Kstride, int Klen, int Ncol,
      const float* __restrict__ bias, float* __restrict__ Cf,
      __half* __restrict__ C16,
      const float* __restrict__ gAB, const int* __restrict__ pairs) {
    using namespace cfg;
    constexpr int BM = 128, BK = 64;
    constexpr int WNG = (BN == 128) ? 4 : 2;
    constexpr int WMG = 8 / WNG;
    constexpr int WTM = BM / WMG;        // 64 (BN=128) or 32 (BN=64)
    constexpr int WTN = BN / WNG;        // 32
    constexpr int MATOMS = WTM / 16;
    constexpr int NAT16 = WTN / 16;      // 2
    constexpr int NATOMS = WTN / 8;      // 4
    constexpr int RB = BM * 128;         // A region per stage
    constexpr int RBB = BN * 128;        // B region per stage
    constexpr int SB = RB + RBB;

    extern __shared__ char smem[];
    const uint32_t sbase = smem_u32(smem);
    const int tid = threadIdx.x;
    const int wid = tid >> 5, lane = tid & 31;
    const int wn = wid % WNG, wm = wid / WNG;
    const int bm0 = blockIdx.y * BM, bn0 = blockIdx.x * BN;
    const int lrow = lane & 15, lhalf = lane >> 4;
    const int kofs = blockIdx.z * Klen;

    float acc[MATOMS][NATOMS][4];
#pragma unroll
    for (int i = 0; i < MATOMS; i++)
#pragma unroll
        for (int j = 0; j < NATOMS; j++)
#pragma unroll
            for (int q = 0; q < 4; q++) acc[i][j][q] = 0.f;

    const __half* Ap = A16 + (size_t)bm0 * Kstride + kofs;
    const __half* Bh = Bhi + (size_t)bn0 * Kstride + kofs;

    auto load_stage = [&](int s, int k0) {
        uint32_t base = sbase + s * SB;
#pragma unroll
        for (int i = 0; i < BM * 8 / 256; i++) {
            int f = tid + i * 256;
            int row = f >> 3, g = f & 7;
            uint32_t d = base + row * 128 + ((g ^ (row & 7)) << 4);
            cpa16(d, Ap + (size_t)row * Kstride + k0 + g * 8);
        }
#pragma unroll
        for (int i = 0; i < BN * 8 / 256; i++) {
            int f = tid + i * 256;
            int row = f >> 3, g = f & 7;
            uint32_t d = base + RB + row * 128 + ((g ^ (row & 7)) << 4);
            cpa16(d, Bh + (size_t)row * Kstride + k0 + g * 8);
        }
    };

    const int nch = Klen / BK;
    load_stage(0, 0);
    cpa_commit();

    for (int ch = 0; ch < nch; ch++) {
        if (ch + 1 < nch) {
            load_stage((ch + 1) & 1, (ch + 1) * BK);
            cpa_commit();
            cpa_wait<1>();
        } else {
            cpa_wait<0>();
        }
        __syncthreads();

        uint32_t sA = sbase + (ch & 1) * SB;
        uint32_t sB = sA + RB;
#pragma unroll
        for (int s = 0; s < 4; s++) {
            uint32_t af[MATOMS][4];
#pragma unroll
            for (int ma = 0; ma < MATOMS; ma++) {
                int row = wm * WTM + ma * 16 + lrow;
                uint32_t off = sA + row * 128 + (((s * 2 + lhalf) ^ (row & 7)) << 4);
                ldsm4(af[ma], off);
            }
            uint32_t bh[NAT16][4];
#pragma unroll
            for (int ng = 0; ng < NAT16; ng++) {
                int rb = wn * WTN + ng * 16 + lrow;
                uint32_t off = sB + rb * 128 + (((s * 2 + lhalf) ^ (rb & 7)) << 4);
                ldsm4(bh[ng], off);
            }
#pragma unroll
            for (int ma = 0; ma < MATOMS; ma++)
#pragma unroll
                for (int na = 0; na < NATOMS; na++)
                    mma_f16(acc[ma][na], af[ma], bh[na >> 1][na & 1],
                            bh[na >> 1][2 + (na & 1)]);
        }
        __syncthreads();
    }

    const int gid = lane >> 2, tig = lane & 3;
#pragma unroll
    for (int ma = 0; ma < MATOMS; ma++) {
        int rowbase = bm0 + wm * WTM + ma * 16;
#pragma unroll
        for (int na = 0; na < NATOMS; na++) {
            int col0 = bn0 + wn * WTN + na * 8 + 2 * tig;
#pragma unroll
            for (int half = 0; half < 2; half++) {
                int row = rowbase + gid + half * 8;
                float v0 = acc[ma][na][half * 2 + 0];
                float v1 = acc[ma][na][half * 2 + 1];
                if (MODE == 2) {
                    int b = row >> 10;          // row = b*P + p, P = 1024
                    int pp = row & 1023;
                    int p0 = pairs[(b * P + pp) * 2 + 0];
                    int p1 = pairs[(b * P + pp) * 2 + 1];
                    const float* ga = gAB + (size_t)(b * NE + p0) * (2 * HID);
                    const float* gb = gAB + (size_t)(b * NE + p1) * (2 * HID) + HID;
                    float r0 = fmaxf(v0 + ga[col0] + gb[col0] + bias[col0], 0.f);
                    float r1 = fmaxf(v1 + ga[col0 + 1] + gb[col0 + 1] + bias[col0 + 1], 0.f);
                    size_t o = (size_t)row * HID + col0;
                    *reinterpret_cast<uint32_t*>(C16 + o) =
                        pkhf(__float2half_rn(r0), __float2half_rn(r1));
                } else {  // MODE 4
                    if (col0 < Ncol)
                        atomicAdd(&Cf[(size_t)row * Ncol + col0], v0);
                    if (col0 + 1 < Ncol)
                        atomicAdd(&Cf[(size_t)row * Ncol + col0 + 1], v1);
                }
            }
        }
    }
}

// ---------------- zero f32 buffer (len % 4 == 0) ----------------
__global__ void k_zero(float* __restrict__ p, int n4) {
    int i = blockIdx.x * blockDim.x + threadIdx.x;
    if (i < n4) reinterpret_cast<float4*>(p)[i] = make_float4(0.f, 0.f, 0.f, 0.f);
}

// ---------------- init out buffer with broadcast bias ----------------
__global__ void k_initout(float* __restrict__ p, const float* __restrict__ b2, int total) {
    using namespace cfg;
    int i = blockIdx.x * blockDim.x + threadIdx.x;
    if (i < total) p[i] = b2[i % OUT];
}

// ---------------- GNN epilogue: h = relu(acc + bias) ----------------
__global__ void k_epignn(const float* __restrict__ acc, const float* __restrict__ bias,
                         float* __restrict__ h) {
    using namespace cfg;
    int i = blockIdx.x * blockDim.x + threadIdx.x;   // over B*N*D
    int row = i / D, col = i - row * D;
    h[i] = fmaxf(acc[(size_t)row * NPG + col] + bias[col], 0.f);
}

// ---------------- weight transpose + fp16 convert (with Ksplit) ----------------
__global__ void k_transW16(const float* __restrict__ W0, const float* __restrict__ Wsf,
                           int Ksplit, int K, int Nsrc,
                           __half* __restrict__ Thi) {
    __shared__ float t[32][33];
    int k0 = blockIdx.x * 32, n0 = blockIdx.y * 32;
    int tx = threadIdx.x, ty = threadIdx.y;
#pragma unroll
    for (int i = 0; i < 4; i++) {
        int k = k0 + ty + i * 8;
        int n = n0 + tx;
        const float* row = (k < Ksplit) ? W0 + (size_t)k * Nsrc
                                        : Wsf + (size_t)(k - Ksplit) * Nsrc;
        t[ty + i * 8][tx] = (n < Nsrc) ? row[n] : 0.f;
    }
    __syncthreads();
#pragma unroll
    for (int i = 0; i < 4; i++) {
        int n = n0 + ty + i * 8;
        int k = k0 + tx;
        Thi[(size_t)n * K + k] = __float2half_rn(t[tx][ty + i * 8]);
    }
}

// ---------------- doc projection ----------------
__global__ void k_docproj(const float* __restrict__ cls, const float* __restrict__ W,
                          const float* __restrict__ bvec, float* __restrict__ out) {
    using namespace cfg;
    int b = blockIdx.y;
    int d = blockIdx.x * blockDim.x + threadIdx.x;
    if (d >= D) return;
    float acc = bvec[d];
    const float* c = cls + b * H;
    for (int h = 0; h < H; h++) acc = fmaf(c[h], W[(size_t)h * D + d], acc);
    out[b * D + d] = fmaxf(acc, 0.f);
}

// ---------------- node features h0 ----------------
__global__ void k_node(const float* __restrict__ token, const float* __restrict__ cls,
                       const int* __restrict__ pos, const float* __restrict__ smask,
                       const int* __restrict__ ner, const float* __restrict__ nmask,
                       const int* __restrict__ ment, const float* __restrict__ nerEmb,
                       const float* __restrict__ docproj, float* __restrict__ h0) {
    using namespace cfg;
    const int n = blockIdx.x, b = blockIdx.y;
    __shared__ int sp[S];
    __shared__ float sm[S];
    int tid = threadIdx.x;
    if (tid < S) {
        sp[tid] = pos[(b * N + n) * S + tid];
        sm[tid] = smask[(b * N + n) * S + tid];
    }
    __syncthreads();
    float* dst = h0 + (size_t)(b * N + n) * D;
    if (n == ment[b]) {
        for (int d = tid; d < D; d += blockDim.x) dst[d] = docproj[b * D + d];
        return;
    }
    float den = 0.1f;
#pragma unroll
    for (int s = 0; s < S; s++) den += sm[s];
    float nm = nmask[b * N + n];
    int nerIdx = ner[b * N + n];
    for (int d = tid; d < D; d += blockDim.x) {
        float v;
        if (d < H) {
            float acc = 0.f;
#pragma unroll
            for (int s = 0; s < S; s++)
                acc = fmaf(token[((size_t)b * T + sp[s]) * H + d], sm[s], acc);
            v = acc / den + cls[b * H + d];
        } else {
            v = nerEmb[nerIdx * NERD + (d - H)];
        }
        dst[d] = v * nm;
    }
}

// ---------------- init A16: slots 0..14 = 0, slot 15 = fp16(h) ----------------
__global__ void k_initA16(const float* __restrict__ hin, __half* __restrict__ A) {
    using namespace cfg;
    size_t i2 = (size_t)blockIdx.x * blockDim.x + threadIdx.x;   // half2 index
    size_t idx = i2 * 2;
    int d = (int)(idx % D);
    size_t rest = idx / D;
    int r = (int)(rest & 15);
    size_t bn = rest >> 4;
    __half2 v = __halves2half2(__float2half_rn(0.f), __float2half_rn(0.f));
    if (r == 15) {
        const float* h = hin + bn * D + d;
        v = __halves2half2(__float2half_rn(h[0]), __float2half_rn(h[1]));
    }
    reinterpret_cast<__half2*>(A)[i2] = v;
}

// ---------------- edge scatter (fp16): A[b,dst,rel,:] += h[b,src,:] ----------------
__global__ void k_scatter16(const float* __restrict__ hin, const int* __restrict__ src,
                            const int* __restrict__ dst, const int* __restrict__ rel,
                            __half* __restrict__ A) {
    using namespace cfg;
    int e = blockIdx.x, b = blockIdx.y;
    int sIdx = src[b * E + e];
    int dIdx = dst[b * E + e];
    int r = rel[b * E + e];
    const float* hrow = hin + (size_t)(b * N + sIdx) * D;
    __half2* arow = reinterpret_cast<__half2*>(
        A + ((size_t)(b * N + dIdx) * 16 + r) * D);
    for (int d2 = threadIdx.x; d2 < D / 2; d2 += blockDim.x) {
        float2 v = *reinterpret_cast<const float2*>(hrow + d2 * 2);
        atomicAdd(&arow[d2],
                  __halves2half2(__float2half_rn(v.x), __float2half_rn(v.y)));
    }
}

// ---------------- entity pooling -> hi/lo fp16 ----------------
__global__ void k_ent(const float* __restrict__ h1, const float* __restrict__ h2,
                      const int* __restrict__ e2m, const float* __restrict__ e2mask,
                      __half* __restrict__ enthi, __half* __restrict__ entlo) {
    using namespace cfg;
    int i = blockIdx.x, b = blockIdx.y;
    __shared__ int idxs[MM];
    __shared__ float mk[MM];
    int tid = threadIdx.x;
    if (tid < MM) {
        idxs[tid] = e2m[(b * NE + i) * MM + tid];
        mk[tid] = e2mask[(b * NE + i) * MM + tid];
    }
    __syncthreads();
    float den = 1e-7f;
#pragma unroll
    for (int j = 0; j < MM; j++) den += mk[j];
    for (int c = tid; c < EE; c += blockDim.x) {
        float acc = 0.f;
#pragma unroll
        for (int j = 0; j < MM; j++) {
            int id = idxs[j];
            if (id > 0) {
                float v = (c < D) ? h1[(size_t)(b * N + id - 1) * D + c]
                                  : h2[(size_t)(b * N + id - 1) * D + (c - D)];
                acc = fmaf(v, mk[j], acc);
            }
        }
        float r = acc / den;
        __half h, l;
        split_f16(r, h, l);
        enthi[(size_t)(b * NE + i) * EE + c] = h;
        entlo[(size_t)(b * NE + i) * EE + c] = l;
    }
}

// ---------------- per-pair nonlinear features -> single fp16 ----------------
__global__ void k_nl(const __half* __restrict__ enthi, const __half* __restrict__ entlo,
                     const int* __restrict__ pairs, __half* __restrict__ nlh) {
    using namespace cfg;
    int p = blockIdx.x, b = blockIdx.y;
    int p0 = pairs[(b * P + p) * 2 + 0];
    int p1 = pairs[(b * P + p) * 2 + 1];
    const __half* hfh = enthi + (size_t)(b * NE + p0) * EE;
    const __half* hfl = entlo + (size_t)(b * NE + p0) * EE;
    const __half* tfh = enthi + (size_t)(b * NE + p1) * EE;
    const __half* tfl = entlo + (size_t)(b * NE + p1) * EE;
    size_t base = ((size_t)b * P + p) * HID;
    for (int c = threadIdx.x; c < EE; c += blockDim.x) {
        float a = __half2float(hfh[c]) + __half2float(hfl[c]);
        float t = __half2float(tfh[c]) + __half2float(tfl[c]);
        nlh[base + c] = __float2half_rn(fabsf(a - t));
        nlh[base + EE + c] = __float2half_rn(a * t);
    }
}

// ---------------- launch ----------------
extern "C" void kernel_launch(void* const* d_in, const int* in_sizes, int n_in,
                              void* d_out, int out_size) {
    using namespace cfg;
    const float* token     = (const float*)d_in[0];
    const float* cls       = (const float*)d_in[1];
    const int*   span_pos  = (const int*)d_in[2];
    const float* span_mask = (const float*)d_in[3];
    const int*   node_ner  = (const int*)d_in[4];
    const float* node_mask = (const float*)d_in[5];
    const int*   e2m       = (const int*)d_in[6];
    const float* e2m_mask  = (const float*)d_in[7];
    const int*   ent_pair  = (const int*)d_in[8];
    const int*   edge_src  = (const int*)d_in[9];
    const int*   edge_dst  = (const int*)d_in[10];
    const int*   edge_rel  = (const int*)d_in[11];
    const int*   ment_num  = (const int*)d_in[12];
    const float* nerEmb    = (const float*)d_in[13];
    const float* doc_W     = (const float*)d_in[14];
    const float* doc_b     = (const float*)d_in[15];
    const float* W_rel     = (const float*)d_in[16];
    const float* W_self    = (const float*)d_in[17];
    const float* gnn_b     = (const float*)d_in[18];
    const float* W1        = (const float*)d_in[19];
    const float* b1        = (const float*)d_in[20];
    const float* W2        = (const float*)d_in[21];
    const float* b2        = (const float*)d_in[22];
    float* out = (float*)d_out;
    (void)in_sizes; (void)n_in; (void)out_size;

    float *pdoc, *ph0, *ph1, *ph2, *pentAB, *pgnnacc;
    __half *pA16, *pWg16_hi, *pent16_hi, *pent16_lo;
    __half *pW1linT16_hi, *pW1nlT16_hi, *pW2T16_hi, *pnlh, *phid16;
    cudaGetSymbolAddress((void**)&pdoc,  g_docproj);
    cudaGetSymbolAddress((void**)&ph0,   g_h0);
    cudaGetSymbolAddress((void**)&ph1,   g_h1);
    cudaGetSymbolAddress((void**)&ph2,   g_h2);
    cudaGetSymbolAddress((void**)&pA16,  g_A16);
    cudaGetSymbolAddress((void**)&pWg16_hi, g_Wg16_hi);
    cudaGetSymbolAddress((void**)&pent16_hi, g_ent16_hi);
    cudaGetSymbolAddress((void**)&pent16_lo, g_ent16_lo);
    cudaGetSymbolAddress((void**)&pW1linT16_hi, g_W1linT16_hi);
    cudaGetSymbolAddress((void**)&pW1nlT16_hi, g_W1nlT16_hi);
    cudaGetSymbolAddress((void**)&pW2T16_hi, g_W2T16_hi);
    cudaGetSymbolAddress((void**)&pentAB, g_entAB);
    cudaGetSymbolAddress((void**)&pnlh, g_nlh);
    cudaGetSymbolAddress((void**)&phid16, g_hid16);
    cudaGetSymbolAddress((void**)&pgnnacc, g_gnnacc);

    constexpr int SMEMP = 2 * (128 * 128 + 128 * 128);  // 65536 (BN=128)
    constexpr int SMEMG = 2 * (128 * 128 + 64 * 128);   // 49152 (BN=64)
    cudaFuncSetAttribute(k_mm2<128, 2>, cudaFuncAttributeMaxDynamicSharedMemorySize, SMEMP);
    cudaFuncSetAttribute(k_mm2<128, 4>, cudaFuncAttributeMaxDynamicSharedMemorySize, SMEMP);
    cudaFuncSetAttribute(k_mm2<64, 4>,  cudaFuncAttributeMaxDynamicSharedMemorySize, SMEMG);

    const dim3 tb(32, 8);

    // 0) one-shot weight transpose + fp16 convert (per launch)
    k_transW16<<<dim3(KG / 32, D / 32), tb>>>(W_rel, W_self, KSPLIT, KG, D, pWg16_hi);
    k_transW16<<<dim3(KG / 32, D / 32), tb>>>(W_rel + (size_t)R * D * D,
                                              W_self + (size_t)D * D, KSPLIT, KG, D,
                                              pWg16_hi + (size_t)NPG * KG);
    k_transW16<<<dim3(EE / 32, HID / 32), tb>>>(W1, W1, EE, EE, HID, pW1linT16_hi);
    k_transW16<<<dim3(EE / 32, HID / 32), tb>>>(W1 + (size_t)EE * HID, W1, EE, EE, HID,
                                                pW1linT16_hi + (size_t)HID * EE);
    k_transW16<<<dim3(HID / 32, HID / 32), tb>>>(W1 + (size_t)2 * EE * HID, W1,
                                                 HID, HID, HID, pW1nlT16_hi);
    k_transW16<<<dim3(HID / 32, 4), tb>>>(W2, W2, HID, HID, OUT, pW2T16_hi);

    // 1) doc projection + node features
    k_docproj<<<dim3((D + 255) / 256, B), 256>>>(cls, doc_W, doc_b, pdoc);
    k_node<<<dim3(N, B), 256>>>(token, cls, span_pos, span_mask, node_ner, node_mask,
                                ment_num, nerEmb, pdoc, ph0);

    const size_t Atotal = (size_t)B * N * 16 * D;   // 13,107,200
    const int initBlocks = (int)(Atotal / 2 / 256); // half2-vectorized
    const int gnnaccN4 = B * N * NPG / 4;           // 212992
    const int entabN4 = B * NE * 2 * HID / 4;       // 409600
    const int outTotal = B * P * OUT;               // 397312
    const int gnnEpiBlocks = (B * N * D) / 256;     // 3200

    // 2) GNN layer 0 (fp16 GEMM, split-K z=4)
    k_initA16<<<initBlocks, 256>>>(ph0, pA16);
    k_scatter16<<<dim3(E, B), 256>>>(ph0, edge_src, edge_dst, edge_rel, pA16);
    k_zero<<<(gnnaccN4 + 255) / 256, 256>>>(pgnnacc, gnnaccN4);
    k_mm2<64, 4><<<dim3(NPG / 64, (B * N) / 128, 4), 256, SMEMG>>>(
        pA16, pWg16_hi, KG, KG / 4, NPG, nullptr, pgnnacc,
        nullptr, nullptr, nullptr);
    k_epignn<<<gnnEpiBlocks, 256>>>(pgnnacc, gnn_b, ph1);

    // 3) GNN layer 1
    k_initA16<<<initBlocks, 256>>>(ph1, pA16);
    k_scatter16<<<dim3(E, B), 256>>>(ph1, edge_src, edge_dst, edge_rel, pA16);
    k_zero<<<(gnnaccN4 + 255) / 256, 256>>>(pgnnacc, gnnaccN4);
    k_mm2<64, 4><<<dim3(NPG / 64, (B * N) / 128, 4), 256, SMEMG>>>(
        pA16, pWg16_hi + (size_t)NPG * KG, KG, KG / 4, NPG, nullptr, pgnnacc,
        nullptr, nullptr, nullptr);
    k_epignn<<<gnnEpiBlocks, 256>>>(pgnnacc, gnn_b + D, ph2);

    // 4) entity pooling (-> fp16 hi/lo)
    k_ent<<<dim3(NE, B), 256>>>(ph1, ph2, e2m, e2m_mask, pent16_hi, pent16_lo);

    // 5) linear halves of pair MLP (fp16, split-K z=5, atomic into entAB)
    k_zero<<<(entabN4 + 255) / 256, 256>>>(pentAB, entabN4);
    k_mm2<128, 4><<<dim3((2 * HID) / 128, (B * NE) / 128, 5), 256, SMEMP>>>(
        pent16_hi, pW1linT16_hi, EE, EE / 5, 2 * HID, nullptr, pentAB,
        nullptr, nullptr, nullptr);

    // 6) nonlinear pair features + fp16 pair GEMM -> hid16
    k_nl<<<dim3(P, B), 256>>>(pent16_hi, pent16_lo, ent_pair, pnlh);
    k_mm2<128, 2><<<dim3(HID / 128, (B * P) / 128, 1), 256, SMEMP>>>(
        pnlh, pW1nlT16_hi, HID, HID, HID, b1, nullptr,
        phid16, pentAB, ent_pair);

    // 7) output layer: init out with b2, then split-K GEMM atomically adds into it
    k_initout<<<(outTotal + 255) / 256, 256>>>(out, b2, outTotal);
    k_mm2<64, 4><<<dim3(2, (B * P) / 128, 5), 256, SMEMG>>>(
        phid16, pW2T16_hi, HID, HID / 5, OUT, nullptr, out,
        nullptr, nullptr, nullptr);
}